// round 1
// baseline (speedup 1.0000x reference)
#include <cuda_runtime.h>
#include <cuda_bf16.h>

// STFT magnitude via packed real-FFT:
//   frame (1024 real) -> z[f] = x[2f] + i*x[2f+1] (512 complex)
//   Z = FFT_512(z)  (radix-2, bit-reversed DIT, twiddle LUT in smem)
//   X[k] = Xe[k] + W_1024^k * Xo[k],  k = 0..512
//   out[b,k,n] = |X[k]|
//
// Matches reference: basis rows are exactly cos(2*pi*k*f/N) and -sin(2*pi*k*f/N),
// i.e. ft real/imag = Re/Im of DFT, magnitude = |DFT(frame)|.

#define N_FFT     1024
#define NH        512      // complex FFT length
#define LOG2_NH   9
#define CUTOFF    513
#define HOP       512
#define T_LEN     2097152
#define N_FRAMES  4095     // (T_LEN - N_FFT)/HOP + 1
#define BATCH     16
#define THREADS   256
#define TILE      32       // frames per block (sequential)
#define SMAG_LD   33       // padded leading dim for mag staging (bank-conflict free)

// dynamic smem layout (floats):
//   smag : CUTOFF * SMAG_LD   = 16929
//   sre  : NH                 = 512
//   sim  : NH                 = 512
//   twr  : NH/2               = 256
//   twi  : NH/2               = 256
#define SMEM_FLOATS (CUTOFF * SMAG_LD + 2 * NH + NH)
#define SMEM_BYTES  (SMEM_FLOATS * 4)

__global__ void __launch_bounds__(THREADS)
stft_mag_kernel(const float* __restrict__ x, float* __restrict__ out)
{
    extern __shared__ float sh[];
    float* smag = sh;                       // [CUTOFF][SMAG_LD]
    float* sre  = sh + CUTOFF * SMAG_LD;    // [NH]
    float* sim  = sre + NH;                 // [NH]
    float* twr  = sim + NH;                 // [NH/2]
    float* twi  = twr + (NH / 2);           // [NH/2]

    const int t  = threadIdx.x;
    const int b  = blockIdx.y;
    const int n0 = blockIdx.x * TILE;
    const int nvalid = min(TILE, N_FRAMES - n0);

    // --- Twiddle LUT: W_512^i = exp(-2*pi*i*j/512), j < 256 ---
    for (int i = t; i < NH / 2; i += THREADS) {
        float s, c;
        sincospif(-(float)i * (1.0f / 256.0f), &s, &c);   // angle = -2*pi*i/512
        twr[i] = c;
        twi[i] = s;
    }
    // (visibility covered by the __syncthreads after the first frame load)

    const float* rowp = x + (size_t)b * T_LEN;

    for (int fl = 0; fl < nvalid; ++fl) {
        const int n = n0 + fl;
        const float2* fp = (const float2*)(rowp + (size_t)n * HOP);  // 1024 floats = 512 float2

        // --- Load packed complex input, bit-reversed placement ---
        #pragma unroll
        for (int r = 0; r < 2; ++r) {
            int f = t + r * THREADS;                 // 0..511
            float2 z = fp[f];
            int bi = __brev((unsigned)f) >> (32 - LOG2_NH);
            sre[bi] = z.x;
            sim[bi] = z.y;
        }
        __syncthreads();

        // --- 9 radix-2 DIT stages (each thread owns 1 butterfly/stage) ---
        #pragma unroll
        for (int s = 1; s <= LOG2_NH; ++s) {
            const int half = 1 << (s - 1);
            const int j    = t & (half - 1);
            const int base = (t >> (s - 1)) << s;
            const int twidx = j << (LOG2_NH - s);
            const float wr = twr[twidx];
            const float wi = twi[twidx];
            const int i0 = base + j;
            const int i1 = i0 + half;
            const float ar = sre[i0], ai = sim[i0];
            const float br = sre[i1], bi = sim[i1];
            const float tr = wr * br - wi * bi;
            const float ti = wr * bi + wi * br;
            sre[i0] = ar + tr;  sim[i0] = ai + ti;
            sre[i1] = ar - tr;  sim[i1] = ai - ti;
            __syncthreads();
        }

        // --- Real-FFT unpack + magnitude, staged to smem tile ---
        for (int k = t; k < CUTOFF; k += THREADS) {
            const int ki = k & (NH - 1);             // k=512 -> 0
            const int km = (NH - k) & (NH - 1);
            const float ar = sre[ki], ai = sim[ki];
            const float br = sre[km], bi = -sim[km]; // conj(Z[512-k])
            const float xer = 0.5f * (ar + br);
            const float xei = 0.5f * (ai + bi);
            const float dr = ar - br;
            const float di = ai - bi;
            const float xor_ = 0.5f * di;            // -i*(A-B)/2
            const float xoi  = -0.5f * dr;
            float ws, wc;
            sincospif(-(float)k * (1.0f / (float)NH), &ws, &wc); // W_1024^k
            const float xr = xer + wc * xor_ - ws * xoi;
            const float xi = xei + wc * xoi + ws * xor_;
            smag[k * SMAG_LD + fl] = sqrtf(xr * xr + xi * xi);
        }
        __syncthreads();   // protect sre/sim reuse next frame + smag completeness
    }

    // --- Coalesced writeback: out[b, k, n0 + j] ---
    const size_t obase = (size_t)b * CUTOFF * N_FRAMES + n0;
    for (int idx = t; idx < CUTOFF * TILE; idx += THREADS) {
        const int k = idx >> 5;        // / 32
        const int j = idx & 31;
        if (j < nvalid)
            out[obase + (size_t)k * N_FRAMES + j] = smag[k * SMAG_LD + j];
    }
}

extern "C" void kernel_launch(void* const* d_in, const int* in_sizes, int n_in,
                              void* d_out, int out_size)
{
    // input_data has 16*2097152 = 33554432 elems; forward_basis has 1026*1024.
    const float* x = (const float*)d_in[0];
    if (n_in > 1 && in_sizes[1] > in_sizes[0]) x = (const float*)d_in[1];

    cudaFuncSetAttribute(stft_mag_kernel,
                         cudaFuncAttributeMaxDynamicSharedMemorySize, SMEM_BYTES);

    dim3 grid((N_FRAMES + TILE - 1) / TILE, BATCH);   // (128, 16)
    stft_mag_kernel<<<grid, THREADS, SMEM_BYTES>>>(x, (float*)d_out);
}

// round 2
// speedup vs baseline: 2.4773x; 2.4773x over previous
#include <cuda_runtime.h>
#include <cuda_bf16.h>

// STFT magnitude via packed real-FFT, radix-8:
//   frame (1024 real) -> z[f] = x[2f] + i*x[2f+1]  (512 complex)
//   Z = FFT_512(z) : 3 radix-8 DIT stages, base-8 digit-reversed input
//   X[k] = Xe[k] + W_1024^k * Xo[k], k = 0..512 ;  out[b,k,n] = |X[k]|
//
// All twiddles from shared LUTs (no per-frame MUFU). FFT data padded
// (addr = i + i/8) for conflict-free stage-0/1 access.

#define N_FFT     1024
#define NH        512
#define CUTOFF    513
#define HOP       512
#define T_LEN     2097152
#define N_FRAMES  4095
#define BATCH     16
#define THREADS   256
#define TILE      32
#define GROUPS    4          // concurrent frames per block (64 threads each)
#define SMAG_LD   33
#define FFT_PAD   576        // PAD(511)=574, rounded up

#define PAD(i) ((i) + ((i) >> 3))

// smem layout (floats):
//   tw   : 512 float2  = 1024   (W_512^t)
//   wk   : 513 float2  = 1026   (W_1024^k)
//   smag : 513*33      = 16929
//   fft  : 4*2*576     = 4608
#define OFF_TW    0
#define OFF_WK    1024
#define OFF_SMAG  2050
#define OFF_FFT   (OFF_SMAG + CUTOFF * SMAG_LD)      // 18979
#define SMEM_FLOATS (OFF_FFT + GROUPS * 2 * FFT_PAD) // 23587
#define SMEM_BYTES  (SMEM_FLOATS * 4)

__device__ __forceinline__ void dft8(float* ur, float* ui)
{
    const float RT = 0.70710678118654752f;
    // even inputs u0,u2,u4,u6
    float t0r = ur[0] + ur[4], t0i = ui[0] + ui[4];
    float t1r = ur[0] - ur[4], t1i = ui[0] - ui[4];
    float t2r = ur[2] + ur[6], t2i = ui[2] + ui[6];
    float d2r = ur[2] - ur[6], d2i = ui[2] - ui[6];
    float t3r =  d2i, t3i = -d2r;                    // -i*(u2-u6)
    float E0r = t0r + t2r, E0i = t0i + t2i;
    float E1r = t1r + t3r, E1i = t1i + t3i;
    float E2r = t0r - t2r, E2i = t0i - t2i;
    float E3r = t1r - t3r, E3i = t1i - t3i;
    // odd inputs u1,u3,u5,u7
    float s0r = ur[1] + ur[5], s0i = ui[1] + ui[5];
    float s1r = ur[1] - ur[5], s1i = ui[1] - ui[5];
    float s2r = ur[3] + ur[7], s2i = ui[3] + ui[7];
    float d3r = ur[3] - ur[7], d3i = ui[3] - ui[7];
    float s3r =  d3i, s3i = -d3r;
    float O0r = s0r + s2r, O0i = s0i + s2i;
    float O1r = s1r + s3r, O1i = s1i + s3i;
    float O2r = s0r - s2r, O2i = s0i - s2i;
    float O3r = s1r - s3r, O3i = s1i - s3i;
    // odd twiddles: W8^1 = r(1-i), W8^2 = -i, W8^3 = -r(1+i)
    float W1r = RT * (O1r + O1i), W1i = RT * (O1i - O1r);
    float W2r = O2i,              W2i = -O2r;
    float W3r = RT * (O3i - O3r), W3i = -RT * (O3r + O3i);
    ur[0] = E0r + O0r; ui[0] = E0i + O0i;
    ur[1] = E1r + W1r; ui[1] = E1i + W1i;
    ur[2] = E2r + W2r; ui[2] = E2i + W2i;
    ur[3] = E3r + W3r; ui[3] = E3i + W3i;
    ur[4] = E0r - O0r; ui[4] = E0i - O0i;
    ur[5] = E1r - W1r; ui[5] = E1i - W1i;
    ur[6] = E2r - W2r; ui[6] = E2i - W2i;
    ur[7] = E3r - W3r; ui[7] = E3i - W3i;
}

__global__ void __launch_bounds__(THREADS)
stft_mag_kernel(const float* __restrict__ x, float* __restrict__ out)
{
    extern __shared__ float sh[];
    float2* tw   = (float2*)(sh + OFF_TW);   // W_512^t, t=0..511
    float2* wk   = (float2*)(sh + OFF_WK);   // W_1024^k, k=0..512
    float*  smag = sh + OFF_SMAG;            // [513][33]
    float*  fft  = sh + OFF_FFT;

    const int t  = threadIdx.x;
    const int g  = t >> 6;                   // group (frame slot) 0..3
    const int gt = t & 63;                   // lane within group
    float* gre = fft + g * (2 * FFT_PAD);
    float* gim = gre + FFT_PAD;

    // --- LUTs (once per block) ---
    for (int i = t; i < NH; i += THREADS) {
        float s, c; sincospif(-(float)i * (1.0f / 256.0f), &s, &c);
        tw[i] = make_float2(c, s);
    }
    for (int i = t; i < CUTOFF; i += THREADS) {
        float s, c; sincospif(-(float)i * (1.0f / 512.0f), &s, &c);
        wk[i] = make_float2(c, s);
    }

    const int b  = blockIdx.y;
    const int n0 = blockIdx.x * TILE;
    const float* rowp = x + (size_t)b * T_LEN;

    #pragma unroll 1
    for (int pass = 0; pass < TILE / GROUPS; ++pass) {
        const int fl = pass * GROUPS + g;
        const int n  = n0 + fl;

        // --- load + base-8 digit-reversed scatter ---
        if (n < N_FRAMES) {
            const float2* fp = (const float2*)(rowp + (size_t)n * HOP);
            #pragma unroll
            for (int i = 0; i < 8; ++i) {
                const int f = gt + i * 64;
                float2 z = fp[f];
                const int rv = ((f & 7) << 6) | (f & 0x38) | (f >> 6);
                const int a = PAD(rv);
                gre[a] = z.x;
                gim[a] = z.y;
            }
        }
        __syncthreads();   // also orders LUT build on pass 0

        // --- stage 0: L=8, contiguous, trivial twiddles ---
        {
            float ur[8], ui[8];
            const int base = gt << 3;
            #pragma unroll
            for (int i = 0; i < 8; ++i) {
                const int a = PAD(base + i);
                ur[i] = gre[a]; ui[i] = gim[a];
            }
            dft8(ur, ui);
            #pragma unroll
            for (int i = 0; i < 8; ++i) {
                const int a = PAD(base + i);
                gre[a] = ur[i]; gim[a] = ui[i];
            }
        }
        __syncthreads();

        // --- stage 1: L=64 (tw step 8), stage 2: L=512 (tw step 1) ---
        #pragma unroll
        for (int m = 1; m < 3; ++m) {
            const int L8   = (m == 1) ? 8 : 64;
            const int step = (m == 1) ? 8 : 1;
            const int j    = gt & (L8 - 1);
            const int blk  = (m == 1) ? (gt >> 3) : 0;
            const int base = blk * (L8 << 3) + j;
            float ur[8], ui[8];
            #pragma unroll
            for (int i = 0; i < 8; ++i) {
                const int a = PAD(base + i * L8);
                const float xr = gre[a], xi = gim[a];
                if (i == 0) { ur[0] = xr; ui[0] = xi; }
                else {
                    const float2 w = tw[i * j * step];
                    ur[i] = xr * w.x - xi * w.y;
                    ui[i] = xr * w.y + xi * w.x;
                }
            }
            dft8(ur, ui);
            #pragma unroll
            for (int i = 0; i < 8; ++i) {
                const int a = PAD(base + i * L8);
                gre[a] = ur[i]; gim[a] = ui[i];
            }
            __syncthreads();
        }

        // --- real-FFT unpack + magnitude -> smag tile ---
        #pragma unroll
        for (int k = gt; k < CUTOFF; k += 64) {
            const int ki = k & (NH - 1);
            const int km = (NH - k) & (NH - 1);
            const int ai = PAD(ki), am = PAD(km);
            const float ar = gre[ai], aim = gim[ai];
            const float br = gre[am], bi = -gim[am];   // conj(Z[512-k])
            const float xer  = 0.5f * (ar + br);
            const float xei  = 0.5f * (aim + bi);
            const float xor_ = 0.5f * (aim - bi);
            const float xoi  = -0.5f * (ar - br);
            const float2 w = wk[k];
            const float xr = xer + w.x * xor_ - w.y * xoi;
            const float xi = xei + w.x * xoi + w.y * xor_;
            smag[k * SMAG_LD + fl] = sqrtf(xr * xr + xi * xi);
        }
        __syncthreads();   // smag done; protect gre/gim for next pass
    }

    // --- coalesced writeback: out[b, k, n0 + j] ---
    const int nvalid = min(TILE, N_FRAMES - n0);
    const size_t obase = (size_t)b * CUTOFF * N_FRAMES + n0;
    for (int idx = t; idx < CUTOFF * TILE; idx += THREADS) {
        const int k = idx >> 5;
        const int j = idx & 31;
        if (j < nvalid)
            out[obase + (size_t)k * N_FRAMES + j] = smag[k * SMAG_LD + j];
    }
}

extern "C" void kernel_launch(void* const* d_in, const int* in_sizes, int n_in,
                              void* d_out, int out_size)
{
    const float* x = (const float*)d_in[0];
    if (n_in > 1 && in_sizes[1] > in_sizes[0]) x = (const float*)d_in[1];

    cudaFuncSetAttribute(stft_mag_kernel,
                         cudaFuncAttributeMaxDynamicSharedMemorySize, SMEM_BYTES);

    dim3 grid((N_FRAMES + TILE - 1) / TILE, BATCH);   // (128, 16)
    stft_mag_kernel<<<grid, THREADS, SMEM_BYTES>>>(x, (float*)d_out);
}

// round 3
// speedup vs baseline: 3.6426x; 1.4704x over previous
#include <cuda_runtime.h>
#include <cuda_bf16.h>

// STFT magnitude, warp-per-frame register FFT:
//   z[f] = x[2f] + i*x[2f+1], FFT_512(z) = FFT16(per-lane regs) x FFT32(cross-lane shfl)
//   X[k] = Xe[k] + W_1024^k * Xo[k];  out[b,k,n] = |X[k]|
// No shared memory in the butterfly path; smem only for twiddle LUT + output staging.

#define NH        512
#define CUTOFF    513
#define HOP       512
#define T_LEN     2097152
#define N_FRAMES  4095
#define BATCH     16
#define THREADS   256
#define TILE      32
#define FPW       4          // frames per warp (8 warps * 4 = 32 = TILE)
#define LD2       545        // staging row stride; 545 % 32 == 1

#define OFF_TW    0                       // float2[512]
#define OFF_WK1   1024                    // float2[16] : W_1024^{k1}
#define OFF_SMAG  1056
#define SMEM_FLOATS (OFF_SMAG + TILE * LD2)   // 18496 floats
#define SMEM_BYTES  (SMEM_FLOATS * 4)         // 73984 B

// after fft16, logical U[k1] (k1 = c + 4d) lives in physical slot 4c + d:
#define SL(k1) ((((k1) & 3) << 2) | ((k1) >> 2))

__device__ __forceinline__ void cmul(float& xr, float& xi, float wr, float wi)
{
    float tr = xr * wr - xi * wi;
    xi = xr * wi + xi * wr;
    xr = tr;
}

__device__ __forceinline__ void dft4(float& r0, float& i0, float& r1, float& i1,
                                     float& r2, float& i2, float& r3, float& i3)
{
    float t0r = r0 + r2, t0i = i0 + i2;
    float t1r = r0 - r2, t1i = i0 - i2;
    float t2r = r1 + r3, t2i = i1 + i3;
    float t3r = r1 - r3, t3i = i1 - i3;
    r0 = t0r + t2r; i0 = t0i + t2i;
    r2 = t0r - t2r; i2 = t0i - t2i;
    r1 = t1r + t3i; i1 = t1i - t3r;   // X1 = t1 - i*t3
    r3 = t1r - t3i; i3 = t1i + t3r;   // X3 = t1 + i*t3
}

__device__ __forceinline__ void fft16(float* ur, float* ui)
{
    // stage 1: DFT4 over b (elements a + 4b)
    #pragma unroll
    for (int a = 0; a < 4; ++a)
        dft4(ur[a], ui[a], ur[a+4], ui[a+4], ur[a+8], ui[a+8], ur[a+12], ui[a+12]);

    const float C1 = 0.9238795325112867f, S1 = 0.3826834323650898f;
    const float R  = 0.7071067811865476f;
    // slot a + 4c  *=  W16^{a*c}
    cmul(ur[5],  ui[5],  C1, -S1);                    // (1,1) W1
    cmul(ur[6],  ui[6],  R,  -R);                     // (2,1) W2
    cmul(ur[7],  ui[7],  S1, -C1);                    // (3,1) W3
    cmul(ur[9],  ui[9],  R,  -R);                     // (1,2) W2
    { float tt = ur[10]; ur[10] = ui[10]; ui[10] = -tt; } // (2,2) W4 = -i
    cmul(ur[11], ui[11], -R, -R);                     // (3,2) W6
    cmul(ur[13], ui[13], S1, -C1);                    // (1,3) W3
    cmul(ur[14], ui[14], -R, -R);                     // (2,3) W6
    cmul(ur[15], ui[15], -C1, S1);                    // (3,3) W9 = -W1

    // stage 2: DFT4 over a (consecutive slots 4c..4c+3)
    #pragma unroll
    for (int c = 0; c < 4; ++c)
        dft4(ur[4*c], ui[4*c], ur[4*c+1], ui[4*c+1],
             ur[4*c+2], ui[4*c+2], ur[4*c+3], ui[4*c+3]);
}

__global__ void __launch_bounds__(THREADS, 2)
stft_mag_kernel(const float* __restrict__ x, float* __restrict__ out)
{
    extern __shared__ float sh[];
    float2* tw512  = (float2*)(sh + OFF_TW);
    float2* wk1lut = (float2*)(sh + OFF_WK1);
    float*  smag   = sh + OFF_SMAG;

    const int t = threadIdx.x;
    const int w = t >> 5;
    const int L = t & 31;

    // --- LUTs: W_512^i and W_1024^{k1} ---
    for (int i = t; i < NH; i += THREADS) {
        float s, c; sincospif(-(float)i * (1.0f / 256.0f), &s, &c);
        tw512[i] = make_float2(c, s);
    }
    if (t < 16) {
        float s, c; sincospif(-(float)t * (1.0f / 512.0f), &s, &c);
        wk1lut[t] = make_float2(c, s);
    }
    __syncthreads();

    // --- per-thread constant twiddles (registers, loaded once) ---
    const int r = __brev((unsigned)L) >> 27;          // this lane's k2 (DIF output order)
    float wk1r[16], wk1i[16];                         // W_512^{L*k1}
    #pragma unroll
    for (int j = 0; j < 16; ++j) {
        float2 v = tw512[(L * j) & 511];
        wk1r[j] = v.x; wk1i[j] = v.y;
    }
    // cross-lane stage twiddles, branchless form: lo lanes -> (1,0), sgn=+1; hi -> W, sgn=-1
    float wstr[5], wsti[5], sgn[5];
    #pragma unroll
    for (int s = 0; s < 5; ++s) {
        int h = 16 >> s;
        if (L & h) {
            float2 v = tw512[((L & (h - 1)) << s) * 16];  // W_32^{j*2^s}
            wstr[s] = v.x; wsti[s] = v.y; sgn[s] = -1.0f;
        } else {
            wstr[s] = 1.0f; wsti[s] = 0.0f; sgn[s] = 1.0f;
        }
    }
    float2 v64 = tw512[8 * r];                        // W_64^{r} = W_1024^{16r}
    const float w64r_ = v64.x, w64i_ = v64.y;
    const int pl0 = __brev((unsigned)((32 - r) & 31)) >> 27;  // slot-0 conj partner lane

    const int b  = blockIdx.y;
    const int n0 = blockIdx.x * TILE;
    const float* rowp = x + (size_t)b * T_LEN;

    #pragma unroll 1
    for (int p = 0; p < FPW; ++p) {
        const int fl = w * FPW + p;
        const int n  = n0 + fl;
        if (n < N_FRAMES) {
            const float2* fp = (const float2*)(rowp + (size_t)n * HOP);
            float ur[16], ui[16];
            #pragma unroll
            for (int j = 0; j < 16; ++j) {               // z[L + 32j], coalesced
                float2 z = fp[L + 32 * j];
                ur[j] = z.x; ui[j] = z.y;
            }

            fft16(ur, ui);

            // twiddle U[k1] *= W_512^{L*k1}
            #pragma unroll
            for (int k1 = 1; k1 < 16; ++k1)
                cmul(ur[SL(k1)], ui[SL(k1)], wk1r[k1], wk1i[k1]);

            // 32-point DIF FFT across lanes (per slot), branchless butterflies
            #pragma unroll
            for (int s = 0; s < 5; ++s) {
                const int h = 16 >> s;
                const float sg = sgn[s], cwr = wstr[s], cwi = wsti[s];
                #pragma unroll
                for (int q = 0; q < 16; ++q) {
                    float orr = __shfl_xor_sync(0xffffffffu, ur[q], h);
                    float ori = __shfl_xor_sync(0xffffffffu, ui[q], h);
                    float dr = fmaf(sg, ur[q], orr);     // lo: a+b ; hi: a-b
                    float di = fmaf(sg, ui[q], ori);
                    ur[q] = dr * cwr - di * cwi;         // lo: *(1,0)
                    ui[q] = dr * cwi + di * cwr;
                }
            }
            // lane L now holds Z[k1 + 16*r] in slot SL(k1), r = brev5(L)

            // real-FFT unpack + magnitude -> staging tile
            float* col = smag + fl * LD2;
            #pragma unroll
            for (int k1 = 0; k1 < 16; ++k1) {
                const int sa = SL(k1);
                const int sb = SL((16 - k1) & 15);
                const int pl = (k1 == 0) ? pl0 : (L ^ 31);
                float Br =  __shfl_sync(0xffffffffu, ur[sb], pl);
                float Bi = -__shfl_sync(0xffffffffu, ui[sb], pl);  // conj(Z[512-k])
                float Ar = ur[sa], Ai = ui[sa];
                float xer  = 0.5f * (Ar + Br);
                float xei  = 0.5f * (Ai + Bi);
                float xor_ = 0.5f * (Ai - Bi);
                float xoi  = -0.5f * (Ar - Br);
                float2 wb = wk1lut[k1];                  // broadcast LDS
                float Wr = wb.x * w64r_ - wb.y * w64i_;  // W_1024^{k1+16r}
                float Wi = wb.x * w64i_ + wb.y * w64r_;
                float Xr = xer + Wr * xor_ - Wi * xoi;
                float Xi = xei + Wr * xoi + Wi * xor_;
                const int k = k1 + 16 * r;
                col[k + (k >> 4)] = sqrtf(Xr * Xr + Xi * Xi);  // swizzled, conflict-free
            }
            if (L == 0)                                   // X[512] = Re(Z0) - Im(Z0)
                col[512 + 32] = fabsf(ur[0] - ui[0]);
        }
    }
    __syncthreads();

    // --- coalesced writeback: out[b, k, n0 + j] ---
    const int nvalid = min(TILE, N_FRAMES - n0);
    const size_t obase = (size_t)b * (size_t)CUTOFF * N_FRAMES + n0;
    for (int idx = t; idx < CUTOFF * TILE; idx += THREADS) {
        const int k = idx >> 5;
        const int j = idx & 31;
        if (j < nvalid)
            out[obase + (size_t)k * N_FRAMES + j] = smag[j * LD2 + k + (k >> 4)];
    }
}

extern "C" void kernel_launch(void* const* d_in, const int* in_sizes, int n_in,
                              void* d_out, int out_size)
{
    const float* x = (const float*)d_in[0];
    if (n_in > 1 && in_sizes[1] > in_sizes[0]) x = (const float*)d_in[1];

    cudaFuncSetAttribute(stft_mag_kernel,
                         cudaFuncAttributeMaxDynamicSharedMemorySize, SMEM_BYTES);

    dim3 grid((N_FRAMES + TILE - 1) / TILE, BATCH);   // (128, 16)
    stft_mag_kernel<<<grid, THREADS, SMEM_BYTES>>>(x, (float*)d_out);
}

// round 4
// speedup vs baseline: 4.1782x; 1.1470x over previous
#include <cuda_runtime.h>
#include <cuda_bf16.h>

// STFT magnitude, warp-per-frame register FFT (occupancy-tuned):
//   z[f] = x[2f] + i*x[2f+1]; FFT_512 = FFT16(in-reg) x FFT32(cross-lane shfl)
//   X[k] = Xe[k] + W_1024^k * Xo[k];  out[b,k,n] = |X[k]|
// Twiddles come from shared tables indexed [slot][lane] (conflict-free) instead of
// per-thread register arrays -> regs drop ~128 -> ~80, 3 CTAs/SM.

#define NH        512
#define CUTOFF    513
#define HOP       512
#define T_LEN     2097152
#define N_FRAMES  4095
#define BATCH     16
#define THREADS   256
#define TILE      16
#define FPW       2          // frames per warp (8 warps * 2 = 16 = TILE)
#define LD2       545        // staging row stride (513 data + swizzle pad); 545%32==1

// smem layout (floats)
#define OFF_WKLUT 0                      // float2[16]      W_1024^{k1}
#define OFF_WKTAB 32                     // float2[16][32]  W_512^{(L*j)&511}
#define OFF_STTAB 1056                   // float2[5][32]   cross-lane stage twiddles
#define OFF_SMAG  1376
#define SMEM_FLOATS (OFF_SMAG + TILE * LD2)   // 10096
#define SMEM_BYTES  (SMEM_FLOATS * 4)         // 40384 B

// after fft16, logical U[k1] (k1 = c + 4d) lives in physical slot 4c + d:
#define SL(k1) ((((k1) & 3) << 2) | ((k1) >> 2))

__device__ __forceinline__ void cmul(float& xr, float& xi, float wr, float wi)
{
    float tr = xr * wr - xi * wi;
    xi = xr * wi + xi * wr;
    xr = tr;
}

__device__ __forceinline__ void dft4(float& r0, float& i0, float& r1, float& i1,
                                     float& r2, float& i2, float& r3, float& i3)
{
    float t0r = r0 + r2, t0i = i0 + i2;
    float t1r = r0 - r2, t1i = i0 - i2;
    float t2r = r1 + r3, t2i = i1 + i3;
    float t3r = r1 - r3, t3i = i1 - i3;
    r0 = t0r + t2r; i0 = t0i + t2i;
    r2 = t0r - t2r; i2 = t0i - t2i;
    r1 = t1r + t3i; i1 = t1i - t3r;   // X1 = t1 - i*t3
    r3 = t1r - t3i; i3 = t1i + t3r;   // X3 = t1 + i*t3
}

__device__ __forceinline__ void fft16(float* ur, float* ui)
{
    #pragma unroll
    for (int a = 0; a < 4; ++a)
        dft4(ur[a], ui[a], ur[a+4], ui[a+4], ur[a+8], ui[a+8], ur[a+12], ui[a+12]);

    const float C1 = 0.9238795325112867f, S1 = 0.3826834323650898f;
    const float R  = 0.7071067811865476f;
    cmul(ur[5],  ui[5],  C1, -S1);
    cmul(ur[6],  ui[6],  R,  -R);
    cmul(ur[7],  ui[7],  S1, -C1);
    cmul(ur[9],  ui[9],  R,  -R);
    { float tt = ur[10]; ur[10] = ui[10]; ui[10] = -tt; }
    cmul(ur[11], ui[11], -R, -R);
    cmul(ur[13], ui[13], S1, -C1);
    cmul(ur[14], ui[14], -R, -R);
    cmul(ur[15], ui[15], -C1, S1);

    #pragma unroll
    for (int c = 0; c < 4; ++c)
        dft4(ur[4*c], ui[4*c], ur[4*c+1], ui[4*c+1],
             ur[4*c+2], ui[4*c+2], ur[4*c+3], ui[4*c+3]);
}

__global__ void __launch_bounds__(THREADS, 3)
stft_mag_kernel(const float* __restrict__ x, float* __restrict__ out)
{
    extern __shared__ float sh[];
    float2* wklut = (float2*)(sh + OFF_WKLUT);   // [16]
    float2* wktab = (float2*)(sh + OFF_WKTAB);   // [16][32] : [j*32 + L]
    float2* sttab = (float2*)(sh + OFF_STTAB);   // [5][32]  : [s*32 + L]
    float*  smag  = sh + OFF_SMAG;

    const int t = threadIdx.x;
    const int w = t >> 5;
    const int L = t & 31;

    // --- build twiddle tables (once per block) ---
    for (int i = t; i < 16 * 32; i += THREADS) {
        const int j = i >> 5, l = i & 31;
        float s, c;
        sincospif(-(float)((l * j) & 511) * (1.0f / 256.0f), &s, &c);  // W_512^{l*j}
        wktab[i] = make_float2(c, s);
    }
    if (t < 5 * 32) {
        const int s = t >> 5, l = t & 31;
        const int h = 16 >> s;
        float2 v = make_float2(1.0f, 0.0f);
        if (l & h) {
            float ss, cc;
            sincospif(-(float)((l & (h - 1)) << s) * (1.0f / 16.0f), &ss, &cc); // W_32^{..}
            v = make_float2(cc, ss);
        }
        sttab[t] = v;
    }
    if (t < 16) {
        float s, c; sincospif(-(float)t * (1.0f / 512.0f), &s, &c);    // W_1024^{k1}
        wklut[t] = make_float2(c, s);
    }
    __syncthreads();

    // --- per-thread constants ---
    const int r = __brev((unsigned)L) >> 27;          // this lane's k2 (DIF output order)
    float w64r_, w64i_;
    { float s, c; sincospif(-(float)r * (1.0f / 32.0f), &s, &c);       // W_64^{r}
      w64r_ = c; w64i_ = s; }
    const int pl0 = __brev((unsigned)((32 - r) & 31)) >> 27;

    const int b  = blockIdx.y;
    const int n0 = blockIdx.x * TILE;
    const float* rowp = x + (size_t)b * T_LEN;

    #pragma unroll 1
    for (int p = 0; p < FPW; ++p) {
        const int fl = w * FPW + p;
        const int n  = n0 + fl;
        if (n < N_FRAMES) {
            const float2* fp = (const float2*)(rowp + (size_t)n * HOP);
            float ur[16], ui[16];
            #pragma unroll
            for (int j = 0; j < 16; ++j) {               // z[L + 32j], coalesced
                float2 z = fp[L + 32 * j];
                ur[j] = z.x; ui[j] = z.y;
            }

            fft16(ur, ui);

            // U[k1] *= W_512^{L*k1}   (twiddle from shared table)
            #pragma unroll
            for (int k1 = 1; k1 < 16; ++k1) {
                float2 wv = wktab[k1 * 32 + L];
                cmul(ur[SL(k1)], ui[SL(k1)], wv.x, wv.y);
            }

            // 32-point DIF FFT across lanes, branchless
            #pragma unroll
            for (int s = 0; s < 5; ++s) {
                const int h = 16 >> s;
                const float2 wst = sttab[s * 32 + L];
                const float sg = __uint_as_float(0x3f800000u |
                                    ((unsigned)(L & h) << (27 + s)));  // lo:+1, hi:-1
                const float cwr = wst.x, cwi = wst.y;
                // hi lanes: (partner - self)*W ; lo lanes: (self + partner)*1
                const float sgn = (L & h) ? -1.0f : 1.0f;  // kept branchless by compiler (FSEL)
                (void)sgn;
                #pragma unroll
                for (int q = 0; q < 16; ++q) {
                    float orr = __shfl_xor_sync(0xffffffffu, ur[q], h);
                    float ori = __shfl_xor_sync(0xffffffffu, ui[q], h);
                    float dr = fmaf(sg, ur[q], orr);
                    float di = fmaf(sg, ui[q], ori);
                    ur[q] = dr * cwr - di * cwi;
                    ui[q] = dr * cwi + di * cwr;
                }
            }
            // lane L holds Z[k1 + 16*r] in slot SL(k1)

            // real-FFT unpack + magnitude -> staging tile
            float* col = smag + fl * LD2;
            #pragma unroll
            for (int k1 = 0; k1 < 16; ++k1) {
                const int sa = SL(k1);
                const int sb = SL((16 - k1) & 15);
                const int pl = (k1 == 0) ? pl0 : (L ^ 31);
                float Br =  __shfl_sync(0xffffffffu, ur[sb], pl);
                float Bi = -__shfl_sync(0xffffffffu, ui[sb], pl);  // conj(Z[512-k])
                float Ar = ur[sa], Ai = ui[sa];
                float xer  = 0.5f * (Ar + Br);
                float xei  = 0.5f * (Ai + Bi);
                float xor_ = 0.5f * (Ai - Bi);
                float xoi  = -0.5f * (Ar - Br);
                float2 wb = wklut[k1];                   // broadcast LDS
                float Wr = wb.x * w64r_ - wb.y * w64i_;  // W_1024^{k1+16r}
                float Wi = wb.x * w64i_ + wb.y * w64r_;
                float Xr = xer + Wr * xor_ - Wi * xoi;
                float Xi = xei + Wr * xoi + Wi * xor_;
                const int k = k1 + 16 * r;
                col[k + (k >> 4)] = sqrtf(Xr * Xr + Xi * Xi);  // swizzled, conflict-free
            }
            if (L == 0)                                   // X[512] = Re(Z0) - Im(Z0)
                col[512 + 32] = fabsf(ur[0] - ui[0]);
        }
    }
    __syncthreads();

    // --- coalesced writeback: out[b, k, n0 + j] ---
    const int nvalid = min(TILE, N_FRAMES - n0);
    const size_t obase = (size_t)b * (size_t)CUTOFF * N_FRAMES + n0;
    for (int idx = t; idx < CUTOFF * TILE; idx += THREADS) {
        const int k = idx >> 4;        // / TILE
        const int j = idx & (TILE - 1);
        if (j < nvalid)
            out[obase + (size_t)k * N_FRAMES + j] = smag[j * LD2 + k + (k >> 4)];
    }
}

extern "C" void kernel_launch(void* const* d_in, const int* in_sizes, int n_in,
                              void* d_out, int out_size)
{
    const float* x = (const float*)d_in[0];
    if (n_in > 1 && in_sizes[1] > in_sizes[0]) x = (const float*)d_in[1];

    cudaFuncSetAttribute(stft_mag_kernel,
                         cudaFuncAttributeMaxDynamicSharedMemorySize, SMEM_BYTES);

    dim3 grid((N_FRAMES + TILE - 1) / TILE, BATCH);   // (256, 16)
    stft_mag_kernel<<<grid, THREADS, SMEM_BYTES>>>(x, (float*)d_out);
}

// round 5
// speedup vs baseline: 4.4112x; 1.0558x over previous
#include <cuda_runtime.h>
#include <cuda_bf16.h>

// STFT magnitude, warp-per-frame register FFT (4 CTA/SM):
//   z[f] = x[2f] + i*x[2f+1]; FFT_512 = FFT16(in-reg) x FFT32(cross-lane shfl)
//   X[k] = Xe[k] + W_1024^k * Xo[k];  out[b,k,n] = |X[k]|
// Twiddles from shared tables; last cross-lane stage specialized (twiddle==1).

#define NH        512
#define CUTOFF    513
#define HOP       512
#define T_LEN     2097152
#define N_FRAMES  4095
#define BATCH     16
#define THREADS   256
#define TILE      16
#define FPW       2          // frames per warp (8 warps * 2 = 16 = TILE)
#define LD2       545        // staging row stride (513 data + swizzle pad); 545%32==1

// smem layout (floats)
#define OFF_WKLUT 0                      // float2[16]      W_1024^{k1}
#define OFF_WKTAB 32                     // float2[16][32]  W_512^{(L*j)&511}
#define OFF_STTAB 1056                   // float2[4][32]   cross-lane stage twiddles (s=0..3)
#define OFF_SMAG  1312
#define SMEM_FLOATS (OFF_SMAG + TILE * LD2)   // 10032
#define SMEM_BYTES  (SMEM_FLOATS * 4)         // 40128 B  (4 CTA x 40KB fits 228KB)

// after fft16, logical U[k1] (k1 = c + 4d) lives in physical slot 4c + d:
#define SL(k1) ((((k1) & 3) << 2) | ((k1) >> 2))

__device__ __forceinline__ void cmul(float& xr, float& xi, float wr, float wi)
{
    float tr = xr * wr - xi * wi;
    xi = xr * wi + xi * wr;
    xr = tr;
}

__device__ __forceinline__ void dft4(float& r0, float& i0, float& r1, float& i1,
                                     float& r2, float& i2, float& r3, float& i3)
{
    float t0r = r0 + r2, t0i = i0 + i2;
    float t1r = r0 - r2, t1i = i0 - i2;
    float t2r = r1 + r3, t2i = i1 + i3;
    float t3r = r1 - r3, t3i = i1 - i3;
    r0 = t0r + t2r; i0 = t0i + t2i;
    r2 = t0r - t2r; i2 = t0i - t2i;
    r1 = t1r + t3i; i1 = t1i - t3r;   // X1 = t1 - i*t3
    r3 = t1r - t3i; i3 = t1i + t3r;   // X3 = t1 + i*t3
}

__device__ __forceinline__ void fft16(float* ur, float* ui)
{
    #pragma unroll
    for (int a = 0; a < 4; ++a)
        dft4(ur[a], ui[a], ur[a+4], ui[a+4], ur[a+8], ui[a+8], ur[a+12], ui[a+12]);

    const float C1 = 0.9238795325112867f, S1 = 0.3826834323650898f;
    const float R  = 0.7071067811865476f;
    cmul(ur[5],  ui[5],  C1, -S1);
    cmul(ur[6],  ui[6],  R,  -R);
    cmul(ur[7],  ui[7],  S1, -C1);
    cmul(ur[9],  ui[9],  R,  -R);
    { float tt = ur[10]; ur[10] = ui[10]; ui[10] = -tt; }
    cmul(ur[11], ui[11], -R, -R);
    cmul(ur[13], ui[13], S1, -C1);
    cmul(ur[14], ui[14], -R, -R);
    cmul(ur[15], ui[15], -C1, S1);

    #pragma unroll
    for (int c = 0; c < 4; ++c)
        dft4(ur[4*c], ui[4*c], ur[4*c+1], ui[4*c+1],
             ur[4*c+2], ui[4*c+2], ur[4*c+3], ui[4*c+3]);
}

__global__ void __launch_bounds__(THREADS, 4)
stft_mag_kernel(const float* __restrict__ x, float* __restrict__ out)
{
    extern __shared__ float sh[];
    float2* wklut = (float2*)(sh + OFF_WKLUT);   // [16]
    float2* wktab = (float2*)(sh + OFF_WKTAB);   // [16][32] : [j*32 + L]
    float2* sttab = (float2*)(sh + OFF_STTAB);   // [4][32]  : [s*32 + L]
    float*  smag  = sh + OFF_SMAG;

    const int t = threadIdx.x;
    const int w = t >> 5;
    const int L = t & 31;

    // --- build twiddle tables (once per block) ---
    for (int i = t; i < 16 * 32; i += THREADS) {
        const int j = i >> 5, l = i & 31;
        float s, c;
        sincospif(-(float)((l * j) & 511) * (1.0f / 256.0f), &s, &c);  // W_512^{l*j}
        wktab[i] = make_float2(c, s);
    }
    if (t < 4 * 32) {
        const int s = t >> 5, l = t & 31;
        const int h = 16 >> s;
        float2 v = make_float2(1.0f, 0.0f);
        if (l & h) {
            float ss, cc;
            sincospif(-(float)((l & (h - 1)) << s) * (1.0f / 16.0f), &ss, &cc); // W_32^{..}
            v = make_float2(cc, ss);
        }
        sttab[t] = v;
    }
    if (t < 16) {
        float s, c; sincospif(-(float)t * (1.0f / 512.0f), &s, &c);    // W_1024^{k1}
        wklut[t] = make_float2(c, s);
    }
    __syncthreads();

    // --- per-thread constants ---
    const int r = __brev((unsigned)L) >> 27;          // this lane's k2 (DIF output order)
    float w64r_, w64i_;
    { float s, c; sincospif(-(float)r * (1.0f / 32.0f), &s, &c);       // W_64^{r}
      w64r_ = c; w64i_ = s; }
    const int pl0 = __brev((unsigned)((32 - r) & 31)) >> 27;

    const int b  = blockIdx.y;
    const int n0 = blockIdx.x * TILE;
    const float* rowp = x + (size_t)b * T_LEN;

    #pragma unroll 1
    for (int p = 0; p < FPW; ++p) {
        const int fl = w * FPW + p;
        const int n  = n0 + fl;
        if (n < N_FRAMES) {
            const float2* fp = (const float2*)(rowp + (size_t)n * HOP);
            float ur[16], ui[16];
            #pragma unroll
            for (int j = 0; j < 16; ++j) {               // z[L + 32j], coalesced
                float2 z = fp[L + 32 * j];
                ur[j] = z.x; ui[j] = z.y;
            }

            fft16(ur, ui);

            // U[k1] *= W_512^{L*k1}   (twiddle from shared table)
            #pragma unroll
            for (int k1 = 1; k1 < 16; ++k1) {
                float2 wv = wktab[k1 * 32 + L];
                cmul(ur[SL(k1)], ui[SL(k1)], wv.x, wv.y);
            }

            // 32-point DIF FFT across lanes: stages 0..3 general
            #pragma unroll
            for (int s = 0; s < 4; ++s) {
                const int h = 16 >> s;
                const float2 wst = sttab[s * 32 + L];
                const float sg = __uint_as_float(0x3f800000u |
                                    ((unsigned)(L & h) << (27 + s)));  // lo:+1, hi:-1
                const float cwr = wst.x, cwi = wst.y;
                #pragma unroll
                for (int q = 0; q < 16; ++q) {
                    float orr = __shfl_xor_sync(0xffffffffu, ur[q], h);
                    float ori = __shfl_xor_sync(0xffffffffu, ui[q], h);
                    float dr = fmaf(sg, ur[q], orr);
                    float di = fmaf(sg, ui[q], ori);
                    ur[q] = dr * cwr - di * cwi;
                    ui[q] = dr * cwi + di * cwr;
                }
            }
            // stage 4 (h=1): twiddle == 1 for every lane — butterfly only
            {
                const float sg = __uint_as_float(0x3f800000u |
                                    ((unsigned)(L & 1) << 31));
                #pragma unroll
                for (int q = 0; q < 16; ++q) {
                    float orr = __shfl_xor_sync(0xffffffffu, ur[q], 1);
                    float ori = __shfl_xor_sync(0xffffffffu, ui[q], 1);
                    ur[q] = fmaf(sg, ur[q], orr);
                    ui[q] = fmaf(sg, ui[q], ori);
                }
            }
            // lane L holds Z[k1 + 16*r] in slot SL(k1)

            // real-FFT unpack + magnitude -> staging tile
            float* col = smag + fl * LD2;
            #pragma unroll
            for (int k1 = 0; k1 < 16; ++k1) {
                const int sa = SL(k1);
                const int sb = SL((16 - k1) & 15);
                const int pl = (k1 == 0) ? pl0 : (L ^ 31);
                float Br =  __shfl_sync(0xffffffffu, ur[sb], pl);
                float Bi = -__shfl_sync(0xffffffffu, ui[sb], pl);  // conj(Z[512-k])
                float Ar = ur[sa], Ai = ui[sa];
                float xer  = 0.5f * (Ar + Br);
                float xei  = 0.5f * (Ai + Bi);
                float xor_ = 0.5f * (Ai - Bi);
                float xoi  = -0.5f * (Ar - Br);
                float2 wb = wklut[k1];                   // broadcast LDS
                float Wr = wb.x * w64r_ - wb.y * w64i_;  // W_1024^{k1+16r}
                float Wi = wb.x * w64i_ + wb.y * w64r_;
                float Xr = xer + Wr * xor_ - Wi * xoi;
                float Xi = xei + Wr * xoi + Wi * xor_;
                const int k = k1 + 16 * r;
                col[k + (k >> 4)] = sqrtf(Xr * Xr + Xi * Xi);  // swizzled, conflict-free
            }
            if (L == 0)                                   // X[512] = Re(Z0) - Im(Z0)
                col[512 + 32] = fabsf(ur[0] - ui[0]);
        }
    }
    __syncthreads();

    // --- coalesced writeback: out[b, k, n0 + j] ---
    const int nvalid = min(TILE, N_FRAMES - n0);
    const size_t obase = (size_t)b * (size_t)CUTOFF * N_FRAMES + n0;
    for (int idx = t; idx < CUTOFF * TILE; idx += THREADS) {
        const int k = idx >> 4;        // / TILE
        const int j = idx & (TILE - 1);
        if (j < nvalid)
            out[obase + (size_t)k * N_FRAMES + j] = smag[j * LD2 + k + (k >> 4)];
    }
}

extern "C" void kernel_launch(void* const* d_in, const int* in_sizes, int n_in,
                              void* d_out, int out_size)
{
    const float* x = (const float*)d_in[0];
    if (n_in > 1 && in_sizes[1] > in_sizes[0]) x = (const float*)d_in[1];

    cudaFuncSetAttribute(stft_mag_kernel,
                         cudaFuncAttributeMaxDynamicSharedMemorySize, SMEM_BYTES);

    dim3 grid((N_FRAMES + TILE - 1) / TILE, BATCH);   // (256, 16)
    stft_mag_kernel<<<grid, THREADS, SMEM_BYTES>>>(x, (float*)d_out);
}

// round 6
// speedup vs baseline: 4.5472x; 1.0308x over previous
#include <cuda_runtime.h>
#include <cuda_bf16.h>

// STFT magnitude, warp-per-frame register FFT (4 CTA/SM, lean epilogue):
//   z[f] = x[2f] + i*x[2f+1]; FFT_512 = FFT16(in-reg) x FFT32(cross-lane shfl)
//   X[k] = Xe[k] + W_1024^k * Xo[k];  out[b,k,n] = |X[k]|
// Unpack twiddles (with the 0.5 factors folded in) come from a per-lane smem
// table; magnitude via x*rsqrt(x).

#define NH        512
#define CUTOFF    513
#define HOP       512
#define T_LEN     2097152
#define N_FRAMES  4095
#define BATCH     16
#define THREADS   256
#define TILE      16
#define FPW       2          // frames per warp (8 warps * 2 = 16 = TILE)
#define LD2       545        // staging row stride (513 data + swizzle pad); 545%32==1

// smem layout (floats)
#define OFF_WKTAB 0                      // float2[16][32]  W_512^{(L*j)&511}
#define OFF_STTAB 1024                   // float2[4][32]   cross-lane stage twiddles (s=0..3)
#define OFF_WUNP  1280                   // float2[16][32]  0.5*W_1024^{k1+16*brev5(L)}
#define OFF_SMAG  2304
#define SMEM_FLOATS (OFF_SMAG + TILE * LD2)   // 11024
#define SMEM_BYTES  (SMEM_FLOATS * 4)         // 44096 B  (4 CTA x 44KB fits 228KB)

// after fft16, logical U[k1] (k1 = c + 4d) lives in physical slot 4c + d:
#define SL(k1) ((((k1) & 3) << 2) | ((k1) >> 2))

__device__ __forceinline__ void cmul(float& xr, float& xi, float wr, float wi)
{
    float tr = xr * wr - xi * wi;
    xi = xr * wi + xi * wr;
    xr = tr;
}

__device__ __forceinline__ void dft4(float& r0, float& i0, float& r1, float& i1,
                                     float& r2, float& i2, float& r3, float& i3)
{
    float t0r = r0 + r2, t0i = i0 + i2;
    float t1r = r0 - r2, t1i = i0 - i2;
    float t2r = r1 + r3, t2i = i1 + i3;
    float t3r = r1 - r3, t3i = i1 - i3;
    r0 = t0r + t2r; i0 = t0i + t2i;
    r2 = t0r - t2r; i2 = t0i - t2i;
    r1 = t1r + t3i; i1 = t1i - t3r;   // X1 = t1 - i*t3
    r3 = t1r - t3i; i3 = t1i + t3r;   // X3 = t1 + i*t3
}

__device__ __forceinline__ void fft16(float* ur, float* ui)
{
    #pragma unroll
    for (int a = 0; a < 4; ++a)
        dft4(ur[a], ui[a], ur[a+4], ui[a+4], ur[a+8], ui[a+8], ur[a+12], ui[a+12]);

    const float C1 = 0.9238795325112867f, S1 = 0.3826834323650898f;
    const float R  = 0.7071067811865476f;
    cmul(ur[5],  ui[5],  C1, -S1);
    cmul(ur[6],  ui[6],  R,  -R);
    cmul(ur[7],  ui[7],  S1, -C1);
    cmul(ur[9],  ui[9],  R,  -R);
    { float tt = ur[10]; ur[10] = ui[10]; ui[10] = -tt; }
    cmul(ur[11], ui[11], -R, -R);
    cmul(ur[13], ui[13], S1, -C1);
    cmul(ur[14], ui[14], -R, -R);
    cmul(ur[15], ui[15], -C1, S1);

    #pragma unroll
    for (int c = 0; c < 4; ++c)
        dft4(ur[4*c], ui[4*c], ur[4*c+1], ui[4*c+1],
             ur[4*c+2], ui[4*c+2], ur[4*c+3], ui[4*c+3]);
}

__global__ void __launch_bounds__(THREADS, 4)
stft_mag_kernel(const float* __restrict__ x, float* __restrict__ out)
{
    extern __shared__ float sh[];
    float2* wktab = (float2*)(sh + OFF_WKTAB);   // [16][32] : [j*32 + L]
    float2* sttab = (float2*)(sh + OFF_STTAB);   // [4][32]  : [s*32 + L]
    float2* wunp  = (float2*)(sh + OFF_WUNP);    // [16][32] : [k1*32 + L]
    float*  smag  = sh + OFF_SMAG;

    const int t = threadIdx.x;
    const int w = t >> 5;
    const int L = t & 31;

    // --- build twiddle tables (once per block) ---
    for (int i = t; i < 16 * 32; i += THREADS) {
        const int j = i >> 5, l = i & 31;
        float s, c;
        sincospif(-(float)((l * j) & 511) * (1.0f / 256.0f), &s, &c);  // W_512^{l*j}
        wktab[i] = make_float2(c, s);
    }
    for (int i = t; i < 16 * 32; i += THREADS) {
        const int k1 = i >> 5, l = i & 31;
        const int rr = __brev((unsigned)l) >> 27;
        float s, c;
        sincospif(-(float)(k1 + 16 * rr) * (1.0f / 512.0f), &s, &c);   // W_1024^{k1+16r}
        wunp[i] = make_float2(0.5f * c, 0.5f * s);
    }
    if (t < 4 * 32) {
        const int s = t >> 5, l = t & 31;
        const int h = 16 >> s;
        float2 v = make_float2(1.0f, 0.0f);
        if (l & h) {
            float ss, cc;
            sincospif(-(float)((l & (h - 1)) << s) * (1.0f / 16.0f), &ss, &cc); // W_32^{..}
            v = make_float2(cc, ss);
        }
        sttab[t] = v;
    }
    __syncthreads();

    // --- per-thread constants ---
    const int r = __brev((unsigned)L) >> 27;          // this lane's k2 (DIF output order)
    const int pl0 = __brev((unsigned)((32 - r) & 31)) >> 27;

    const int b  = blockIdx.y;
    const int n0 = blockIdx.x * TILE;
    const float* rowp = x + (size_t)b * T_LEN;

    #pragma unroll 1
    for (int p = 0; p < FPW; ++p) {
        const int fl = w * FPW + p;
        const int n  = n0 + fl;
        if (n < N_FRAMES) {
            const float2* fp = (const float2*)(rowp + (size_t)n * HOP);
            float ur[16], ui[16];
            #pragma unroll
            for (int j = 0; j < 16; ++j) {               // z[L + 32j], coalesced
                float2 z = fp[L + 32 * j];
                ur[j] = z.x; ui[j] = z.y;
            }

            fft16(ur, ui);

            // U[k1] *= W_512^{L*k1}   (twiddle from shared table)
            #pragma unroll
            for (int k1 = 1; k1 < 16; ++k1) {
                float2 wv = wktab[k1 * 32 + L];
                cmul(ur[SL(k1)], ui[SL(k1)], wv.x, wv.y);
            }

            // 32-point DIF FFT across lanes: stages 0..3 general
            #pragma unroll
            for (int s = 0; s < 4; ++s) {
                const int h = 16 >> s;
                const float2 wst = sttab[s * 32 + L];
                const float sg = __uint_as_float(0x3f800000u |
                                    ((unsigned)(L & h) << (27 + s)));  // lo:+1, hi:-1
                const float cwr = wst.x, cwi = wst.y;
                #pragma unroll
                for (int q = 0; q < 16; ++q) {
                    float orr = __shfl_xor_sync(0xffffffffu, ur[q], h);
                    float ori = __shfl_xor_sync(0xffffffffu, ui[q], h);
                    float dr = fmaf(sg, ur[q], orr);
                    float di = fmaf(sg, ui[q], ori);
                    ur[q] = dr * cwr - di * cwi;
                    ui[q] = dr * cwi + di * cwr;
                }
            }
            // stage 4 (h=1): twiddle == 1 for every lane — butterfly only
            {
                const float sg = __uint_as_float(0x3f800000u |
                                    ((unsigned)(L & 1) << 31));
                #pragma unroll
                for (int q = 0; q < 16; ++q) {
                    float orr = __shfl_xor_sync(0xffffffffu, ur[q], 1);
                    float ori = __shfl_xor_sync(0xffffffffu, ui[q], 1);
                    ur[q] = fmaf(sg, ur[q], orr);
                    ui[q] = fmaf(sg, ui[q], ori);
                }
            }
            // lane L holds Z[k1 + 16*r] in slot SL(k1)

            // real-FFT unpack + magnitude -> staging tile
            //   A = Z[k], B = conj(Z[512-k]); with W' = 0.5*W_1024^k:
            //   u=Ar+Br, q=Ar-Br, p=Ai+Bi, v=Ai-Bi
            //   Xr = 0.5u + W'r*v + W'i*q ;  Xi = 0.5p - W'r*q + W'i*v
            float* col = smag + fl * LD2;
            #pragma unroll
            for (int k1 = 0; k1 < 16; ++k1) {
                const int sa = SL(k1);
                const int sb = SL((16 - k1) & 15);
                const int pl = (k1 == 0) ? pl0 : (L ^ 31);
                float Br = __shfl_sync(0xffffffffu, ur[sb], pl);
                float Bs = __shfl_sync(0xffffffffu, ui[sb], pl);   // = -Bi
                float Ar = ur[sa], Ai = ui[sa];
                float uu = Ar + Br, qq = Ar - Br;
                float pp = Ai - Bs, vv = Ai + Bs;
                float2 wv = wunp[k1 * 32 + L];
                float Xr = fmaf(wv.x, vv, fmaf(wv.y, qq, 0.5f * uu));
                float Xi = fmaf(wv.y, vv, fmaf(-wv.x, qq, 0.5f * pp));
                float s2 = fmaf(Xr, Xr, Xi * Xi);
                float mag = s2 * rsqrtf(fmaxf(s2, 1e-37f));
                const int k = k1 + 16 * r;
                col[k + (k >> 4)] = mag;                 // swizzled, conflict-free
            }
            if (L == 0)                                   // X[512] = Re(Z0) - Im(Z0)
                col[512 + 32] = fabsf(ur[0] - ui[0]);
        }
    }
    __syncthreads();

    // --- coalesced writeback: out[b, k, n0 + j] ---
    const int nvalid = min(TILE, N_FRAMES - n0);
    const size_t obase = (size_t)b * (size_t)CUTOFF * N_FRAMES + n0;
    for (int idx = t; idx < CUTOFF * TILE; idx += THREADS) {
        const int k = idx >> 4;        // / TILE
        const int j = idx & (TILE - 1);
        if (j < nvalid)
            out[obase + (size_t)k * N_FRAMES + j] = smag[j * LD2 + k + (k >> 4)];
    }
}

extern "C" void kernel_launch(void* const* d_in, const int* in_sizes, int n_in,
                              void* d_out, int out_size)
{
    const float* x = (const float*)d_in[0];
    if (n_in > 1 && in_sizes[1] > in_sizes[0]) x = (const float*)d_in[1];

    cudaFuncSetAttribute(stft_mag_kernel,
                         cudaFuncAttributeMaxDynamicSharedMemorySize, SMEM_BYTES);

    dim3 grid((N_FRAMES + TILE - 1) / TILE, BATCH);   // (256, 16)
    stft_mag_kernel<<<grid, THREADS, SMEM_BYTES>>>(x, (float*)d_out);
}